// round 15
// baseline (speedup 1.0000x reference)
#include <cuda_runtime.h>
#include <cuda_bf16.h>

// MeanAggregator: out[i] = mean over edges e with segment_ids[e]==i of
// features[neighbor_idx[e]], zero row if no edges. segment_ids is SORTED.
//
// Inputs (metadata order) — JAX x64 disabled => indices are int32:
//   d_in[0] features     float32 [N=50000, D=128]
//   d_in[1] neighbor_idx int32   [E=1600000]
//   d_in[2] segment_ids  int32   [E=1600000]  (sorted ascending)
// Output: float32 [N, D]

#define MAX_NODES 50001

__device__ int g_row_start[MAX_NODES + 1];  // row_start[i] = first edge of segment i

// --- Kernel 1: segment boundaries from sorted segment_ids -------------------
__global__ void boundary_kernel(const int* __restrict__ seg, int E, int N) {
    int e = blockIdx.x * blockDim.x + threadIdx.x;
    if (e > E) return;
    int prev = (e == 0) ? -1 : seg[e - 1];
    int cur  = (e == E) ? N : seg[e];
    if (cur > N) cur = N;           // defensive clamp
    for (int s = prev + 1; s <= cur; s++) {
        g_row_start[s] = e;
    }
}

// --- Kernel 2: one warp per node, float4 per lane (512B row per warp) -------
// 8-wide MLP, tree-reduced accumulation, next-batch index prefetch.
__global__ void __launch_bounds__(256, 6) mean_agg_kernel(
    const float4* __restrict__ features,      // [N, 32] float4
    const int* __restrict__ neighbor,         // [E]
    float4* __restrict__ out,                 // [N, 32] float4
    int N)
{
    int warp_in_blk = threadIdx.x >> 5;
    int lane        = threadIdx.x & 31;
    int node        = blockIdx.x * 8 + warp_in_blk;
    if (node >= N) return;

    int s = g_row_start[node];
    int e = g_row_start[node + 1];
    int cnt = e - s;

    float4 acc0 = make_float4(0.f, 0.f, 0.f, 0.f);
    float4 acc1 = make_float4(0.f, 0.f, 0.f, 0.f);

    // prefetch first batch of indices
    int myidx = 0;
    if (s + lane < e) myidx = __ldg(&neighbor[s + lane]);

    for (int base = s; base < e; base += 32) {
        int n = e - base;
        if (n > 32) n = 32;
        int curidx = myidx;
        // prefetch next batch's indices while this batch computes
        int nb = base + 32;
        if (nb + lane < e) myidx = __ldg(&neighbor[nb + lane]);

        int j = 0;
        for (; j + 8 <= n; j += 8) {
            int i0 = __shfl_sync(0xffffffffu, curidx, j + 0);
            int i1 = __shfl_sync(0xffffffffu, curidx, j + 1);
            int i2 = __shfl_sync(0xffffffffu, curidx, j + 2);
            int i3 = __shfl_sync(0xffffffffu, curidx, j + 3);
            int i4 = __shfl_sync(0xffffffffu, curidx, j + 4);
            int i5 = __shfl_sync(0xffffffffu, curidx, j + 5);
            int i6 = __shfl_sync(0xffffffffu, curidx, j + 6);
            int i7 = __shfl_sync(0xffffffffu, curidx, j + 7);
            float4 f0 = __ldg(&features[(long long)i0 * 32 + lane]);
            float4 f1 = __ldg(&features[(long long)i1 * 32 + lane]);
            float4 f2 = __ldg(&features[(long long)i2 * 32 + lane]);
            float4 f3 = __ldg(&features[(long long)i3 * 32 + lane]);
            float4 f4 = __ldg(&features[(long long)i4 * 32 + lane]);
            float4 f5 = __ldg(&features[(long long)i5 * 32 + lane]);
            float4 f6 = __ldg(&features[(long long)i6 * 32 + lane]);
            float4 f7 = __ldg(&features[(long long)i7 * 32 + lane]);
            // tree add: pairwise sums (independent), then two accumulators
            float4 s01, s23, s45, s67;
            s01.x = f0.x + f1.x; s01.y = f0.y + f1.y; s01.z = f0.z + f1.z; s01.w = f0.w + f1.w;
            s23.x = f2.x + f3.x; s23.y = f2.y + f3.y; s23.z = f2.z + f3.z; s23.w = f2.w + f3.w;
            s45.x = f4.x + f5.x; s45.y = f4.y + f5.y; s45.z = f4.z + f5.z; s45.w = f4.w + f5.w;
            s67.x = f6.x + f7.x; s67.y = f6.y + f7.y; s67.z = f6.z + f7.z; s67.w = f6.w + f7.w;
            acc0.x += s01.x + s23.x; acc0.y += s01.y + s23.y;
            acc0.z += s01.z + s23.z; acc0.w += s01.w + s23.w;
            acc1.x += s45.x + s67.x; acc1.y += s45.y + s67.y;
            acc1.z += s45.z + s67.z; acc1.w += s45.w + s67.w;
        }
        for (; j < n; j++) {
            int i0 = __shfl_sync(0xffffffffu, curidx, j);
            float4 f0 = __ldg(&features[(long long)i0 * 32 + lane]);
            acc0.x += f0.x; acc0.y += f0.y; acc0.z += f0.z; acc0.w += f0.w;
        }
    }

    float inv = (cnt > 0) ? (1.0f / (float)cnt) : 0.0f;
    float4 r;
    r.x = (acc0.x + acc1.x) * inv;
    r.y = (acc0.y + acc1.y) * inv;
    r.z = (acc0.z + acc1.z) * inv;
    r.w = (acc0.w + acc1.w) * inv;
    out[(long long)node * 32 + lane] = r;
}

extern "C" void kernel_launch(void* const* d_in, const int* in_sizes, int n_in,
                              void* d_out, int out_size) {
    const float* features = (const float*)d_in[0];
    const int*   neighbor = (const int*)d_in[1];
    const int*   seg      = (const int*)d_in[2];
    float*       out      = (float*)d_out;

    int E = in_sizes[1];            // 1600000
    int N = out_size / 128;         // 50000
    if (N > MAX_NODES) N = MAX_NODES;

    // Kernel 1: segment boundaries
    {
        int threads = 256;
        int blocks  = (E + 1 + threads - 1) / threads;
        boundary_kernel<<<blocks, threads>>>(seg, E, N);
    }
    // Kernel 2: aggregation, one warp per node
    {
        int threads = 256;                 // 8 warps = 8 nodes per block
        int blocks  = (N + 7) / 8;
        mean_agg_kernel<<<blocks, threads>>>(
            (const float4*)features, neighbor, (float4*)out, N);
    }
}